// round 11
// baseline (speedup 1.0000x reference)
#include <cuda_runtime.h>
#include <cstdint>
#include <cstddef>

// ---------------------------------------------------------------------------
// LlamaDecoderLayer fp32. GEMMs + attention via portable mma.sync tf32.
// B operands stream directly from original W[K,N]. BK=32 pipeline.
// T=2048, D=2048, NH=32, NKV=8, HD=64, FF=8192.
// ---------------------------------------------------------------------------

#define T_LEN 2048
#define DMODEL 2048
#define NHEAD 32
#define NKV 8
#define HD 64
#define FF 8192
#define QKV_N 3072
#define GU_N 16384

// ---- scratch -------------------------------------------------------------
__device__ float g_xn  [T_LEN * DMODEL];     // h1 exact (residual)
__device__ float g_xnt [T_LEN * DMODEL];     // h1 tf32-rounded (GEMM A)
__device__ float g_qkv [T_LEN * QKV_N];
__device__ float g_att [T_LEN * DMODEL];     // attention out, tf32-rounded
__device__ float g_h2  [T_LEN * DMODEL];
__device__ float g_h3  [T_LEN * DMODEL];     // exact (residual)
__device__ float g_h3t [T_LEN * DMODEL];     // rounded (GEMM A)
__device__ float g_gu  [T_LEN * GU_N];       // gate | up (raw)
__device__ float g_gb  [T_LEN * FF];         // silu(gate)*up, rounded
__device__ float g_rt  [T_LEN * 64];         // rope table: (cos,sin) x 32 per row

// ---------------------------------------------------------------------------
// helpers
// ---------------------------------------------------------------------------
__device__ __forceinline__ uint32_t smem_u32(const void* p) {
    uint32_t a;
    asm("{ .reg .u64 t; cvta.to.shared.u64 t, %1; cvt.u32.u64 %0, t; }" : "=r"(a) : "l"(p));
    return a;
}
__device__ __forceinline__ float to_tf32(float x) {
    asm("cvt.rna.tf32.f32 %0, %1;" : "=f"(x) : "f"(x));
    return x;
}
#define CP16(sm_addr, gptr) \
    asm volatile("cp.async.cg.shared.global [%0], [%1], 16;" :: "r"(sm_addr), "l"(gptr))
#define CP_COMMIT() asm volatile("cp.async.commit_group;")
#define CP_WAIT1()  asm volatile("cp.async.wait_group 1;")

__device__ __forceinline__ void mma_f(float* c, const float* a, const float* b) {
    asm volatile("mma.sync.aligned.m16n8k8.row.col.f32.tf32.tf32.f32 "
                 "{%0,%1,%2,%3}, {%4,%5,%6,%7}, {%8,%9}, {%0,%1,%2,%3};"
                 : "+f"(c[0]), "+f"(c[1]), "+f"(c[2]), "+f"(c[3])
                 : "r"(__float_as_uint(a[0])), "r"(__float_as_uint(a[1])),
                   "r"(__float_as_uint(a[2])), "r"(__float_as_uint(a[3])),
                   "r"(__float_as_uint(b[0])), "r"(__float_as_uint(b[1])));
}

// ---------------------------------------------------------------------------
// rope table: row t, d=0..31 -> (cos, sin)
// ---------------------------------------------------------------------------
__global__ __launch_bounds__(256) void rope_table_k(float* __restrict__ rt)
{
    int i = blockIdx.x * blockDim.x + threadIdx.x;
    int t = i >> 5, d = i & 31;
    double freq = exp((double)(-2.0 * d / 64.0) * 9.210340371976184);
    double si, co;
    sincos(freq * (double)t, &si, &co);
    ((float2*)rt)[i] = make_float2((float)co, (float)si);
}

// ---------------------------------------------------------------------------
// tf32 tensor-core GEMM: C[M,Nc] = A[M,K] @ Wsel[K,*]  (+add0 +add1)
// B streamed directly from row-major W. CTA 128x256, BK=32, 3-stage cp.async.
// 8 warps x (64x64). Three B sources; epilogue: 0=none, 1=rope.
// ---------------------------------------------------------------------------
#define ASTRIDE 36                             // 32 + 4 pad
#define BSTRIDE 264                            // 256 + 8 pad
#define A_BYTES (128 * ASTRIDE * 4)            // 18432
#define B_BYTES (32 * BSTRIDE * 4)             // 33792
#define STG_B   (A_BYTES + B_BYTES)            // 52224
#define GSM_TOTAL (3 * STG_B)                  // 156672

__global__ __launch_bounds__(256, 1) void tgemm_k(const float* __restrict__ A,
                                                  const float* __restrict__ B0,
                                                  const float* __restrict__ B1,
                                                  const float* __restrict__ B2,
                                                  float* __restrict__ C,
                                                  int M, int Nc, int K,
                                                  int sB0, int sB1, int sB2,
                                                  int blk1, int blk2,
                                                  const float* __restrict__ add0,
                                                  const float* __restrict__ add1,
                                                  int epi,
                                                  const float* __restrict__ epi_src)
{
    extern __shared__ char sm[];
    const uint32_t smb = smem_u32(sm);
    const int tid = threadIdx.x;
    const int wid = tid >> 5, lane = tid & 31;
    const int warp_m = wid & 1;
    const int warp_n = wid >> 1;
    const int bx = blockIdx.x;
    const int brow = blockIdx.y * 128;
    const int bcol = bx * 256;

    const float* B; int strideB, bcolB;
    if (bx < blk1)      { B = B0; strideB = sB0; bcolB = bx * 256; }
    else if (bx < blk2) { B = B1; strideB = sB1; bcolB = (bx - blk1) * 256; }
    else                { B = B2; strideB = sB2; bcolB = (bx - blk2) * 256; }

    // A loader: thread t -> row t>>1, 16 cols at (t&1)*16, 4x CP16
    const float* aG = A + (size_t)(brow + (tid >> 1)) * K + (tid & 1) * 16;
    const uint32_t sA0 = smb + (tid >> 1) * (ASTRIDE * 4) + (tid & 1) * 64;
    // B loader: thread t -> k-row t>>3, 32 cols at (t&7)*32, 8x CP16
    const int bkr = tid >> 3, bc = (tid & 7) * 32;
    const float* bG = B + (size_t)bkr * strideB + bcolB + bc;
    const uint32_t sB0a = smb + A_BYTES + (bkr * BSTRIDE + bc) * 4;

    float c[4][8][4];
    #pragma unroll
    for (int mi = 0; mi < 4; mi++)
        #pragma unroll
        for (int ni = 0; ni < 8; ni++)
            #pragma unroll
            for (int j = 0; j < 4; j++) c[mi][ni][j] = 0.f;

    const int nk = K >> 5;

    #pragma unroll
    for (int p = 0; p < 2; p++) {
        const float* a0 = aG + p * 32;
        const float* b0 = bG + (size_t)p * 32 * strideB;
        uint32_t sa = sA0 + p * STG_B;
        uint32_t sb = sB0a + p * STG_B;
        #pragma unroll
        for (int j = 0; j < 4; j++) CP16(sa + j * 16, a0 + j * 4);
        #pragma unroll
        for (int j = 0; j < 8; j++) CP16(sb + j * 16, b0 + j * 4);
        CP_COMMIT();
    }

    const int r1 = lane >> 2, cq = lane & 3;

    for (int kt = 0; kt < nk; kt++) {
        CP_WAIT1();
        __syncthreads();

        if (kt + 2 < nk) {
            int st = (kt + 2) % 3;
            const float* a0 = aG + (size_t)(kt + 2) * 32;
            const float* b0 = bG + (size_t)(kt + 2) * 32 * strideB;
            uint32_t sa = sA0 + st * STG_B;
            uint32_t sb = sB0a + st * STG_B;
            #pragma unroll
            for (int j = 0; j < 4; j++) CP16(sa + j * 16, a0 + j * 4);
            #pragma unroll
            for (int j = 0; j < 8; j++) CP16(sb + j * 16, b0 + j * 4);
        }
        CP_COMMIT();

        const float* As = (const float*)(sm + (kt % 3) * STG_B);
        const float* Bs = As + A_BYTES / 4;
        const float* abase = As + (warp_m * 64 + r1) * ASTRIDE + cq;

        #pragma unroll
        for (int kk = 0; kk < 4; kk++) {
            float a[4][4], b[8][2];
            #pragma unroll
            for (int mi = 0; mi < 4; mi++) {
                const float* ap = abase + mi * 16 * ASTRIDE + kk * 8;
                a[mi][0] = ap[0];
                a[mi][1] = ap[8 * ASTRIDE];
                a[mi][2] = ap[4];
                a[mi][3] = ap[8 * ASTRIDE + 4];
            }
            const float* bp = Bs + (kk * 8 + cq) * BSTRIDE + warp_n * 64 + r1;
            #pragma unroll
            for (int ni = 0; ni < 8; ni++) {
                b[ni][0] = bp[ni * 8];
                b[ni][1] = bp[4 * BSTRIDE + ni * 8];
            }
            #pragma unroll
            for (int mi = 0; mi < 4; mi++)
                #pragma unroll
                for (int ni = 0; ni < 8; ni++)
                    mma_f(c[mi][ni], a[mi], b[ni]);
        }
    }

    // ---- epilogue ----
    #pragma unroll
    for (int mi = 0; mi < 4; mi++) {
        #pragma unroll
        for (int part = 0; part < 2; part++) {
            int r = brow + warp_m * 64 + mi * 16 + r1 + part * 8;
            size_t rowbase = (size_t)r * Nc;
            #pragma unroll
            for (int ni = 0; ni < 8; ni++) {
                int col = bcol + warp_n * 64 + ni * 8 + cq * 2;
                float2 v = make_float2(c[mi][ni][part * 2], c[mi][ni][part * 2 + 1]);
                if (epi == 1) {
                    if (col < 2560) {   // rope on q (0..2047) and k (2048..2559)
                        int dp = (col & 63) >> 1;
                        float2 cssn = ((const float2*)epi_src)[r * 32 + dp];
                        float x1 = v.x, x2 = v.y;
                        v.x = x1 * cssn.x - x2 * cssn.y;
                        v.y = x2 * cssn.x + x1 * cssn.y;
                    }
                }
                if (add0) { const float2 a2 = *(const float2*)&add0[rowbase + col];
                            v.x += a2.x; v.y += a2.y; }
                if (add1) { const float2 a2 = *(const float2*)&add1[rowbase + col];
                            v.x += a2.x; v.y += a2.y; }
                *(float2*)&C[rowbase + col] = v;
            }
        }
    }
}

// ---------------------------------------------------------------------------
// Tensor-core flash attention (causal GQA).
// ---------------------------------------------------------------------------
#define ATT_SMEM_FLOATS (4352 + 4352 + 4608 + 4352)
#define ATT_SMEM_BYTES  (ATT_SMEM_FLOATS * 4)

__global__ __launch_bounds__(128) void attn_tc_k(const float* __restrict__ QKV,
                                                 float* __restrict__ Oa)
{
    extern __shared__ float s[];
    float* qsm = s;                  // [64][68]
    float* ksm = s + 4352;           // [64][68]
    float* vsm = s + 8704;           // [64][72]
    float* psm = s + 13312;          // [4][16][68]

    const int tid = threadIdx.x;
    const int w = tid >> 5, lane = tid & 31;
    const int r1 = lane >> 2, cq = lane & 3;
    const int qt = blockIdx.x, h = blockIdx.y;
    const int kvh = h >> 2;

    {
        const float* qb = QKV + (size_t)(qt * 64) * QKV_N + h * HD;
        for (int t = tid; t < 1024; t += 128) {
            int i = t >> 4, d4 = (t & 15) * 4;
            float4 v4 = *(const float4*)(qb + (size_t)i * QKV_N + d4);
            v4.x = to_tf32(v4.x); v4.y = to_tf32(v4.y);
            v4.z = to_tf32(v4.z); v4.w = to_tf32(v4.w);
            *(float4*)(qsm + i * 68 + d4) = v4;
        }
    }
    __syncthreads();

    float qf[8][4];
    {
        const float* qb = qsm + (w * 16 + r1) * 68 + cq;
        #pragma unroll
        for (int ks = 0; ks < 8; ks++) {
            qf[ks][0] = qb[ks * 8];
            qf[ks][1] = qb[8 * 68 + ks * 8];
            qf[ks][2] = qb[ks * 8 + 4];
            qf[ks][3] = qb[8 * 68 + ks * 8 + 4];
        }
    }

    float oA[8][4];
    #pragma unroll
    for (int nt = 0; nt < 8; nt++)
        #pragma unroll
        for (int j = 0; j < 4; j++) oA[nt][j] = 0.f;
    float m0 = -1e30f, m1 = -1e30f, l0 = 0.f, l1 = 0.f;

    float* pb = psm + w * 16 * 68;

    for (int jt = 0; jt <= qt; jt++) {
        __syncthreads();
        {
            const float* kb = QKV + (size_t)(jt * 64) * QKV_N + DMODEL + kvh * HD;
            const float* vb = kb + 512;
            for (int t = tid; t < 1024; t += 128) {
                int i = t >> 4, d4 = (t & 15) * 4;
                float4 k4 = *(const float4*)(kb + (size_t)i * QKV_N + d4);
                k4.x = to_tf32(k4.x); k4.y = to_tf32(k4.y);
                k4.z = to_tf32(k4.z); k4.w = to_tf32(k4.w);
                *(float4*)(ksm + i * 68 + d4) = k4;
                float4 v4 = *(const float4*)(vb + (size_t)i * QKV_N + d4);
                v4.x = to_tf32(v4.x); v4.y = to_tf32(v4.y);
                v4.z = to_tf32(v4.z); v4.w = to_tf32(v4.w);
                *(float4*)(vsm + i * 72 + d4) = v4;
            }
        }
        __syncthreads();

        float sA[8][4];
        #pragma unroll
        for (int nt = 0; nt < 8; nt++) {
            float acc[4] = {0.f, 0.f, 0.f, 0.f};
            const float* kbp = ksm + (nt * 8 + r1) * 68 + cq;
            #pragma unroll
            for (int ks = 0; ks < 8; ks++) {
                float bf[2] = { kbp[ks * 8], kbp[ks * 8 + 4] };
                mma_f(acc, qf[ks], bf);
            }
            sA[nt][0] = acc[0]; sA[nt][1] = acc[1];
            sA[nt][2] = acc[2]; sA[nt][3] = acc[3];
        }

        float mn0 = m0, mn1 = m1;
        const int row0 = w * 16 + r1, row1 = row0 + 8;
        #pragma unroll
        for (int nt = 0; nt < 8; nt++) {
            #pragma unroll
            for (int j = 0; j < 4; j++) sA[nt][j] *= 0.125f;
            if (jt == qt) {
                int colb = nt * 8 + 2 * cq;
                if (colb     > row0) sA[nt][0] = -1e30f;
                if (colb + 1 > row0) sA[nt][1] = -1e30f;
                if (colb     > row1) sA[nt][2] = -1e30f;
                if (colb + 1 > row1) sA[nt][3] = -1e30f;
            }
            mn0 = fmaxf(mn0, fmaxf(sA[nt][0], sA[nt][1]));
            mn1 = fmaxf(mn1, fmaxf(sA[nt][2], sA[nt][3]));
        }
        mn0 = fmaxf(mn0, __shfl_xor_sync(0xffffffffu, mn0, 1));
        mn0 = fmaxf(mn0, __shfl_xor_sync(0xffffffffu, mn0, 2));
        mn1 = fmaxf(mn1, __shfl_xor_sync(0xffffffffu, mn1, 1));
        mn1 = fmaxf(mn1, __shfl_xor_sync(0xffffffffu, mn1, 2));

        float c0 = __expf(m0 - mn0), c1 = __expf(m1 - mn1);
        m0 = mn0; m1 = mn1;

        float ls0 = 0.f, ls1 = 0.f;
        #pragma unroll
        for (int nt = 0; nt < 8; nt++) {
            float p0 = to_tf32(__expf(sA[nt][0] - mn0));
            float p1 = to_tf32(__expf(sA[nt][1] - mn0));
            float p2 = to_tf32(__expf(sA[nt][2] - mn1));
            float p3 = to_tf32(__expf(sA[nt][3] - mn1));
            ls0 += p0 + p1; ls1 += p2 + p3;
            int cb = nt * 8 + 2 * cq;
            pb[r1 * 68 + cb]       = p0;
            pb[r1 * 68 + cb + 1]   = p1;
            pb[(r1 + 8) * 68 + cb]     = p2;
            pb[(r1 + 8) * 68 + cb + 1] = p3;
        }
        ls0 += __shfl_xor_sync(0xffffffffu, ls0, 1);
        ls0 += __shfl_xor_sync(0xffffffffu, ls0, 2);
        ls1 += __shfl_xor_sync(0xffffffffu, ls1, 1);
        ls1 += __shfl_xor_sync(0xffffffffu, ls1, 2);
        l0 = l0 * c0 + ls0;
        l1 = l1 * c1 + ls1;

        #pragma unroll
        for (int nt = 0; nt < 8; nt++) {
            oA[nt][0] *= c0; oA[nt][1] *= c0;
            oA[nt][2] *= c1; oA[nt][3] *= c1;
        }
        __syncwarp();

        #pragma unroll
        for (int ks = 0; ks < 8; ks++) {
            float af[4];
            af[0] = pb[r1 * 68 + ks * 8 + cq];
            af[1] = pb[(r1 + 8) * 68 + ks * 8 + cq];
            af[2] = pb[r1 * 68 + ks * 8 + cq + 4];
            af[3] = pb[(r1 + 8) * 68 + ks * 8 + cq + 4];
            const float* vb0 = vsm + (ks * 8 + cq) * 72 + r1;
            const float* vb1 = vsm + (ks * 8 + cq + 4) * 72 + r1;
            #pragma unroll
            for (int nt = 0; nt < 8; nt++) {
                float bf[2] = { vb0[nt * 8], vb1[nt * 8] };
                mma_f(oA[nt], af, bf);
            }
        }
    }

    float inv0 = 1.f / l0, inv1 = 1.f / l1;
    int gr0 = qt * 64 + w * 16 + r1;
    #pragma unroll
    for (int nt = 0; nt < 8; nt++) {
        int col = h * HD + nt * 8 + 2 * cq;
        float2 v0 = make_float2(to_tf32(oA[nt][0] * inv0), to_tf32(oA[nt][1] * inv0));
        float2 v1 = make_float2(to_tf32(oA[nt][2] * inv1), to_tf32(oA[nt][3] * inv1));
        *(float2*)&Oa[(size_t)gr0 * DMODEL + col] = v0;
        *(float2*)&Oa[(size_t)(gr0 + 8) * DMODEL + col] = v1;
    }
}

// ---------------------------------------------------------------------------
// RMSNorm: out exact, outT tf32-rounded
// ---------------------------------------------------------------------------
__global__ __launch_bounds__(256) void rmsnorm_k(const float* __restrict__ x,
                                                 const float* __restrict__ g,
                                                 float* __restrict__ out,
                                                 float* __restrict__ outT)
{
    int row = blockIdx.x;
    int tid = threadIdx.x;
    const float4* xr4 = (const float4*)(x + (size_t)row * DMODEL);
    const float4* g4  = (const float4*)g;

    float4 a = xr4[tid];
    float4 b = xr4[tid + 256];
    float s = a.x*a.x + a.y*a.y + a.z*a.z + a.w*a.w
            + b.x*b.x + b.y*b.y + b.z*b.z + b.w*b.w;
    #pragma unroll
    for (int off = 16; off > 0; off >>= 1) s += __shfl_xor_sync(0xffffffffu, s, off);

    __shared__ float red[8];
    __shared__ float inv_s;
    int wid = tid >> 5, lane = tid & 31;
    if (lane == 0) red[wid] = s;
    __syncthreads();
    if (tid == 0) {
        float t = 0.f;
        #pragma unroll
        for (int w = 0; w < 8; w++) t += red[w];
        inv_s = rsqrtf(t / (float)DMODEL + 1e-5f);
    }
    __syncthreads();
    float inv = inv_s;

    float4 ga = g4[tid], gb = g4[tid + 256];
    float4 ra, rb;
    ra.x = a.x*ga.x*inv; ra.y = a.y*ga.y*inv; ra.z = a.z*ga.z*inv; ra.w = a.w*ga.w*inv;
    rb.x = b.x*gb.x*inv; rb.y = b.y*gb.y*inv; rb.z = b.z*gb.z*inv; rb.w = b.w*gb.w*inv;
    ((float4*)(out + (size_t)row * DMODEL))[tid] = ra;
    ((float4*)(out + (size_t)row * DMODEL))[tid + 256] = rb;
    if (outT) {
        float4 ta = make_float4(to_tf32(ra.x), to_tf32(ra.y), to_tf32(ra.z), to_tf32(ra.w));
        float4 tb = make_float4(to_tf32(rb.x), to_tf32(rb.y), to_tf32(rb.z), to_tf32(rb.w));
        ((float4*)(outT + (size_t)row * DMODEL))[tid] = ta;
        ((float4*)(outT + (size_t)row * DMODEL))[tid + 256] = tb;
    }
}

// ---------------------------------------------------------------------------
// silu(gate)*up from fused gu buffer [T,16384] -> gb [T,8192] (tf32-rounded)
// ---------------------------------------------------------------------------
__global__ __launch_bounds__(256) void silu_mul_k(const float* __restrict__ gu,
                                                  float* __restrict__ gb)
{
    int i = blockIdx.x * blockDim.x + threadIdx.x;   // over T*FF/4
    int row  = i >> 11;
    int col4 = i & 2047;
    const float4 a = ((const float4*)(gu + (size_t)row * GU_N))[col4];
    const float4 b = ((const float4*)(gu + (size_t)row * GU_N + FF))[col4];
    float4 r;
    r.x = to_tf32(a.x / (1.f + __expf(-a.x)) * b.x);
    r.y = to_tf32(a.y / (1.f + __expf(-a.y)) * b.y);
    r.z = to_tf32(a.z / (1.f + __expf(-a.z)) * b.z);
    r.w = to_tf32(a.w / (1.f + __expf(-a.w)) * b.w);
    ((float4*)(gb + (size_t)row * FF))[col4] = r;
}

// ---------------------------------------------------------------------------
// kernel_launch
// ---------------------------------------------------------------------------
extern "C" void kernel_launch(void* const* d_in, const int* in_sizes, int n_in,
                              void* d_out, int out_size)
{
    (void)in_sizes; (void)n_in; (void)out_size;
    const float* x  = (const float*)d_in[0];
    const float* g1 = (const float*)d_in[1];
    const float* wq = (const float*)d_in[2];
    const float* wk = (const float*)d_in[3];
    const float* wv = (const float*)d_in[4];
    const float* wo = (const float*)d_in[5];
    const float* g2 = (const float*)d_in[6];
    const float* wg = (const float*)d_in[7];
    const float* wu = (const float*)d_in[8];
    const float* wd = (const float*)d_in[9];
    float* out = (float*)d_out;

    float *xn, *xnt, *qkv, *att, *h2, *h3, *h3t, *gu, *gb, *rt;
    cudaGetSymbolAddress((void**)&xn,   g_xn);
    cudaGetSymbolAddress((void**)&xnt,  g_xnt);
    cudaGetSymbolAddress((void**)&qkv,  g_qkv);
    cudaGetSymbolAddress((void**)&att,  g_att);
    cudaGetSymbolAddress((void**)&h2,   g_h2);
    cudaGetSymbolAddress((void**)&h3,   g_h3);
    cudaGetSymbolAddress((void**)&h3t,  g_h3t);
    cudaGetSymbolAddress((void**)&gu,   g_gu);
    cudaGetSymbolAddress((void**)&gb,   g_gb);
    cudaGetSymbolAddress((void**)&rt,   g_rt);

    cudaFuncSetAttribute(tgemm_k,   cudaFuncAttributeMaxDynamicSharedMemorySize, GSM_TOTAL);
    cudaFuncSetAttribute(attn_tc_k, cudaFuncAttributeMaxDynamicSharedMemorySize, ATT_SMEM_BYTES);

    // rope table + h1 = rmsnorm(x, g1)
    rope_table_k<<<T_LEN * 32 / 256, 256>>>(rt);
    rmsnorm_k<<<T_LEN, 256>>>(x, g1, xn, xnt);

    // qkv = h1t @ [wq|wk|wv], rope fused into epilogue
    tgemm_k<<<dim3(QKV_N/256, T_LEN/128), 256, GSM_TOTAL>>>(
        xnt, wq, wk, wv, qkv, T_LEN, QKV_N, DMODEL,
        DMODEL, 512, 512, 8, 10, nullptr, nullptr, 1, rt);

    attn_tc_k<<<dim3(T_LEN/64, NHEAD), 128, ATT_SMEM_BYTES>>>(qkv, att);

    // h2 = h1 + att @ wo
    tgemm_k<<<dim3(DMODEL/256, T_LEN/128), 256, GSM_TOTAL>>>(
        att, wo, wo, wo, h2, T_LEN, DMODEL, DMODEL,
        DMODEL, DMODEL, DMODEL, 9999, 9999, xn, nullptr, 0, nullptr);

    rmsnorm_k<<<T_LEN, 256>>>(h2, g2, h3, h3t);

    // gu = h3t @ [wg|wu]  (merged: 1024 tiles -> ~99% wave efficiency)
    tgemm_k<<<dim3(GU_N/256, T_LEN/128), 256, GSM_TOTAL>>>(
        h3t, wg, wu, wu, gu, T_LEN, GU_N, DMODEL,
        FF, FF, FF, 32, 64, nullptr, nullptr, 0, nullptr);

    // gb = tf32(silu(gate) * up)
    int n4 = T_LEN * FF / 4;
    silu_mul_k<<<n4 / 256, 256>>>(gu, gb);

    // out = gb @ wd + h3 + x
    tgemm_k<<<dim3(DMODEL/256, T_LEN/128), 256, GSM_TOTAL>>>(
        gb, wd, wd, wd, out, T_LEN, DMODEL, FF,
        DMODEL, DMODEL, DMODEL, 9999, 9999, h3, x, 0, nullptr);
}

// round 12
// speedup vs baseline: 1.2022x; 1.2022x over previous
#include <cuda_runtime.h>
#include <cstdint>
#include <cstddef>

// ---------------------------------------------------------------------------
// LlamaDecoderLayer fp32. GEMMs + attention via portable mma.sync tf32.
// B operands stream directly from original W[K,N] (no transpose pass).
// T=2048, D=2048, NH=32, NKV=8, HD=64, FF=8192.
// ---------------------------------------------------------------------------

#define T_LEN 2048
#define DMODEL 2048
#define NHEAD 32
#define NKV 8
#define HD 64
#define FF 8192
#define QKV_N 3072

// ---- scratch -------------------------------------------------------------
__device__ float g_xn  [T_LEN * DMODEL];     // h1 exact (residual)
__device__ float g_xnt [T_LEN * DMODEL];     // h1 tf32-rounded (GEMM A)
__device__ float g_qkv [T_LEN * QKV_N];
__device__ float g_att [T_LEN * DMODEL];     // attention out, tf32-rounded
__device__ float g_h2  [T_LEN * DMODEL];
__device__ float g_h3  [T_LEN * DMODEL];     // exact (residual)
__device__ float g_h3t [T_LEN * DMODEL];     // rounded (GEMM A)
__device__ float g_gate[T_LEN * FF];         // h3t @ wg (raw)
__device__ float g_gb  [T_LEN * FF];         // silu(gate)*up, rounded
__device__ float g_rt  [T_LEN * 64];         // rope table: (cos,sin) x 32 per row

// ---------------------------------------------------------------------------
// helpers
// ---------------------------------------------------------------------------
__device__ __forceinline__ uint32_t smem_u32(const void* p) {
    uint32_t a;
    asm("{ .reg .u64 t; cvta.to.shared.u64 t, %1; cvt.u32.u64 %0, t; }" : "=r"(a) : "l"(p));
    return a;
}
__device__ __forceinline__ float to_tf32(float x) {
    asm("cvt.rna.tf32.f32 %0, %1;" : "=f"(x) : "f"(x));
    return x;
}
#define CP16(sm_addr, gptr) \
    asm volatile("cp.async.cg.shared.global [%0], [%1], 16;" :: "r"(sm_addr), "l"(gptr))
#define CP_COMMIT() asm volatile("cp.async.commit_group;")
#define CP_WAIT1()  asm volatile("cp.async.wait_group 1;")

__device__ __forceinline__ void mma_f(float* c, const float* a, const float* b) {
    asm volatile("mma.sync.aligned.m16n8k8.row.col.f32.tf32.tf32.f32 "
                 "{%0,%1,%2,%3}, {%4,%5,%6,%7}, {%8,%9}, {%0,%1,%2,%3};"
                 : "+f"(c[0]), "+f"(c[1]), "+f"(c[2]), "+f"(c[3])
                 : "r"(__float_as_uint(a[0])), "r"(__float_as_uint(a[1])),
                   "r"(__float_as_uint(a[2])), "r"(__float_as_uint(a[3])),
                   "r"(__float_as_uint(b[0])), "r"(__float_as_uint(b[1])));
}

// ---------------------------------------------------------------------------
// rope table: row t, d=0..31 -> (cos, sin)
// ---------------------------------------------------------------------------
__global__ __launch_bounds__(256) void rope_table_k(float* __restrict__ rt)
{
    int i = blockIdx.x * blockDim.x + threadIdx.x;   // over T*32
    int t = i >> 5, d = i & 31;
    double freq = exp((double)(-2.0 * d / 64.0) * 9.210340371976184);
    double si, co;
    sincos(freq * (double)t, &si, &co);
    ((float2*)rt)[i] = make_float2((float)co, (float)si);
}

// ---------------------------------------------------------------------------
// tf32 tensor-core GEMM (exact R10 configuration: BK=16, 3-stage, 2 CTA/SM).
// C[M,Nc] = A[M,K] @ Wsel[K,*]  (+add0 +add1). Epilogue: 0=none, 1=rope, 2=silu.
// ---------------------------------------------------------------------------
#define ASTRIDE 20
#define BSTRIDE 264
#define A_BYTES (128 * ASTRIDE * 4)          // 10240
#define B_BYTES (16 * BSTRIDE * 4)           // 16896
#define STG_B   (A_BYTES + B_BYTES)          // 27136
#define GSM_TOTAL (3 * STG_B)                // 81408

__global__ __launch_bounds__(256, 1) void tgemm_k(const float* __restrict__ A,
                                                  const float* __restrict__ B0,
                                                  const float* __restrict__ B1,
                                                  const float* __restrict__ B2,
                                                  float* __restrict__ C,
                                                  int M, int Nc, int K,
                                                  int sB0, int sB1, int sB2,
                                                  int blk1, int blk2,
                                                  const float* __restrict__ add0,
                                                  const float* __restrict__ add1,
                                                  int epi,
                                                  const float* __restrict__ epi_src)
{
    extern __shared__ char sm[];
    const uint32_t smb = smem_u32(sm);
    const int tid = threadIdx.x;
    const int wid = tid >> 5, lane = tid & 31;
    const int warp_m = wid & 1;
    const int warp_n = wid >> 1;
    const int bx = blockIdx.x;
    const int brow = blockIdx.y * 128;
    const int bcol = bx * 256;

    const float* B; int strideB, bcolB;
    if (bx < blk1)      { B = B0; strideB = sB0; bcolB = bx * 256; }
    else if (bx < blk2) { B = B1; strideB = sB1; bcolB = (bx - blk1) * 256; }
    else                { B = B2; strideB = sB2; bcolB = (bx - blk2) * 256; }

    // A loader: thread t -> row t>>1, cols (t&1)*8, 2x CP16
    const float* aG = A + (size_t)(brow + (tid >> 1)) * K + (tid & 1) * 8;
    const uint32_t sA0 = smb + (tid >> 1) * (ASTRIDE * 4) + (tid & 1) * 32;
    // B loader: thread t -> k-row t>>4, col chunk (t&15)*4, 4x CP16 at +64 floats
    const int bkr = tid >> 4, bc4 = (tid & 15) * 4;
    const float* bG = B + (size_t)bkr * strideB + bcolB + bc4;
    const uint32_t sB0a = smb + A_BYTES + (bkr * BSTRIDE + bc4) * 4;

    float c[4][8][4];
    #pragma unroll
    for (int mi = 0; mi < 4; mi++)
        #pragma unroll
        for (int ni = 0; ni < 8; ni++)
            #pragma unroll
            for (int j = 0; j < 4; j++) c[mi][ni][j] = 0.f;

    const int nk = K >> 4;

    #pragma unroll
    for (int p = 0; p < 2; p++) {
        const float* a0 = aG + p * 16;
        const float* b0 = bG + (size_t)p * 16 * strideB;
        uint32_t sa = sA0 + p * STG_B;
        uint32_t sb = sB0a + p * STG_B;
        CP16(sa, a0); CP16(sa + 16, a0 + 4);
        #pragma unroll
        for (int j = 0; j < 4; j++) CP16(sb + j * 256, b0 + j * 64);
        CP_COMMIT();
    }

    const int r1 = lane >> 2, cq = lane & 3;

    for (int kt = 0; kt < nk; kt++) {
        CP_WAIT1();
        __syncthreads();

        if (kt + 2 < nk) {
            int st = (kt + 2) % 3;
            const float* a0 = aG + (size_t)(kt + 2) * 16;
            const float* b0 = bG + (size_t)(kt + 2) * 16 * strideB;
            uint32_t sa = sA0 + st * STG_B;
            uint32_t sb = sB0a + st * STG_B;
            CP16(sa, a0); CP16(sa + 16, a0 + 4);
            #pragma unroll
            for (int j = 0; j < 4; j++) CP16(sb + j * 256, b0 + j * 64);
        }
        CP_COMMIT();

        const float* As = (const float*)(sm + (kt % 3) * STG_B);
        const float* Bs = As + A_BYTES / 4;
        const float* abase = As + (warp_m * 64 + r1) * ASTRIDE + cq;

        #pragma unroll
        for (int kk = 0; kk < 2; kk++) {
            float a[4][4], b[8][2];
            #pragma unroll
            for (int mi = 0; mi < 4; mi++) {
                const float* ap = abase + mi * 16 * ASTRIDE + kk * 8;
                a[mi][0] = ap[0];
                a[mi][1] = ap[8 * ASTRIDE];
                a[mi][2] = ap[4];
                a[mi][3] = ap[8 * ASTRIDE + 4];
            }
            const float* bp = Bs + (kk * 8 + cq) * BSTRIDE + warp_n * 64 + r1;
            #pragma unroll
            for (int ni = 0; ni < 8; ni++) {
                b[ni][0] = bp[ni * 8];
                b[ni][1] = bp[4 * BSTRIDE + ni * 8];
            }
            #pragma unroll
            for (int mi = 0; mi < 4; mi++)
                #pragma unroll
                for (int ni = 0; ni < 8; ni++)
                    mma_f(c[mi][ni], a[mi], b[ni]);
        }
    }

    // ---- epilogue ----
    #pragma unroll
    for (int mi = 0; mi < 4; mi++) {
        #pragma unroll
        for (int part = 0; part < 2; part++) {
            int r = brow + warp_m * 64 + mi * 16 + r1 + part * 8;
            size_t rowbase = (size_t)r * Nc;
            #pragma unroll
            for (int ni = 0; ni < 8; ni++) {
                int col = bcol + warp_n * 64 + ni * 8 + cq * 2;
                float2 v = make_float2(c[mi][ni][part * 2], c[mi][ni][part * 2 + 1]);
                if (epi == 1) {
                    if (col < 2560) {   // rope on q (0..2047) and k (2048..2559)
                        int dp = (col & 63) >> 1;
                        float2 cssn = ((const float2*)epi_src)[r * 32 + dp];
                        float x1 = v.x, x2 = v.y;
                        v.x = x1 * cssn.x - x2 * cssn.y;
                        v.y = x2 * cssn.x + x1 * cssn.y;
                    }
                } else if (epi == 2) {  // v = up; combine with gate
                    const float2 gt = *(const float2*)&epi_src[rowbase + col];
                    v.x = to_tf32(gt.x / (1.f + __expf(-gt.x)) * v.x);
                    v.y = to_tf32(gt.y / (1.f + __expf(-gt.y)) * v.y);
                }
                if (add0) { const float2 a2 = *(const float2*)&add0[rowbase + col];
                            v.x += a2.x; v.y += a2.y; }
                if (add1) { const float2 a2 = *(const float2*)&add1[rowbase + col];
                            v.x += a2.x; v.y += a2.y; }
                *(float2*)&C[rowbase + col] = v;
            }
        }
    }
}

// ---------------------------------------------------------------------------
// Tensor-core flash attention (causal GQA).
// Block = 128 q rows (2 q-tiles) x 1 head, 256 threads = 2 warp groups of 4.
// Both groups share the K/V tiles in smem (half the loads + syncs per mma).
// smem floats: qsm 128x68 | ksm 64x68 | vsm 64x72 | psm 8x16x68
// ---------------------------------------------------------------------------
#define ATT_SMEM_FLOATS (8704 + 4352 + 4608 + 8704)
#define ATT_SMEM_BYTES  (ATT_SMEM_FLOATS * 4)

__global__ __launch_bounds__(256) void attn_tc_k(const float* __restrict__ QKV,
                                                 float* __restrict__ Oa)
{
    extern __shared__ float s[];
    float* qsm = s;                  // [128][68]
    float* ksm = s + 8704;           // [64][68]
    float* vsm = s + 13056;          // [64][72]
    float* psm = s + 17664;          // [8][16][68]

    const int tid = threadIdx.x;
    const int w = tid >> 5, lane = tid & 31;
    const int grp = w >> 2;          // 0 or 1: which q-tile
    const int wg  = w & 3;           // warp within group
    const int r1 = lane >> 2, cq = lane & 3;
    const int qp = blockIdx.x, h = blockIdx.y;
    const int myqt = qp * 2 + grp;
    const int kvh = h >> 2;

    // ---- load 128 q rows (rounded) ----
    {
        const float* qb = QKV + (size_t)(qp * 128) * QKV_N + h * HD;
        for (int t = tid; t < 2048; t += 256) {
            int i = t >> 4, d4 = (t & 15) * 4;
            float4 v4 = *(const float4*)(qb + (size_t)i * QKV_N + d4);
            v4.x = to_tf32(v4.x); v4.y = to_tf32(v4.y);
            v4.z = to_tf32(v4.z); v4.w = to_tf32(v4.w);
            *(float4*)(qsm + i * 68 + d4) = v4;
        }
    }
    __syncthreads();

    // ---- Q fragments: rows grp*64 + wg*16 + r1 (+8) ----
    float qf[8][4];
    {
        const float* qb = qsm + (grp * 64 + wg * 16 + r1) * 68 + cq;
        #pragma unroll
        for (int ks = 0; ks < 8; ks++) {
            qf[ks][0] = qb[ks * 8];
            qf[ks][1] = qb[8 * 68 + ks * 8];
            qf[ks][2] = qb[ks * 8 + 4];
            qf[ks][3] = qb[8 * 68 + ks * 8 + 4];
        }
    }

    float oA[8][4];
    #pragma unroll
    for (int nt = 0; nt < 8; nt++)
        #pragma unroll
        for (int j = 0; j < 4; j++) oA[nt][j] = 0.f;
    float m0 = -1e30f, m1 = -1e30f, l0 = 0.f, l1 = 0.f;

    float* pb = psm + w * 16 * 68;
    const int njt = qp * 2 + 1;      // last jt (group 1's diagonal)

    for (int jt = 0; jt <= njt; jt++) {
        __syncthreads();
        {
            const float* kb = QKV + (size_t)(jt * 64) * QKV_N + DMODEL + kvh * HD;
            const float* vb = kb + 512;
            for (int t = tid; t < 1024; t += 256) {
                int i = t >> 4, d4 = (t & 15) * 4;
                float4 k4 = *(const float4*)(kb + (size_t)i * QKV_N + d4);
                k4.x = to_tf32(k4.x); k4.y = to_tf32(k4.y);
                k4.z = to_tf32(k4.z); k4.w = to_tf32(k4.w);
                *(float4*)(ksm + i * 68 + d4) = k4;
                float4 v4 = *(const float4*)(vb + (size_t)i * QKV_N + d4);
                v4.x = to_tf32(v4.x); v4.y = to_tf32(v4.y);
                v4.z = to_tf32(v4.z); v4.w = to_tf32(v4.w);
                *(float4*)(vsm + i * 72 + d4) = v4;
            }
        }
        __syncthreads();

        if (jt > myqt) continue;     // group 0 idles on group 1's diagonal tile

        // ---- S = Q @ K^T ----
        float sA[8][4];
        #pragma unroll
        for (int nt = 0; nt < 8; nt++) {
            float acc[4] = {0.f, 0.f, 0.f, 0.f};
            const float* kbp = ksm + (nt * 8 + r1) * 68 + cq;
            #pragma unroll
            for (int ks = 0; ks < 8; ks++) {
                float bf[2] = { kbp[ks * 8], kbp[ks * 8 + 4] };
                mma_f(acc, qf[ks], bf);
            }
            sA[nt][0] = acc[0]; sA[nt][1] = acc[1];
            sA[nt][2] = acc[2]; sA[nt][3] = acc[3];
        }

        // ---- scale + causal mask + row max ----
        float mn0 = m0, mn1 = m1;
        const int row0 = wg * 16 + r1, row1 = row0 + 8;
        #pragma unroll
        for (int nt = 0; nt < 8; nt++) {
            #pragma unroll
            for (int j = 0; j < 4; j++) sA[nt][j] *= 0.125f;
            if (jt == myqt) {
                int colb = nt * 8 + 2 * cq;
                if (colb     > row0) sA[nt][0] = -1e30f;
                if (colb + 1 > row0) sA[nt][1] = -1e30f;
                if (colb     > row1) sA[nt][2] = -1e30f;
                if (colb + 1 > row1) sA[nt][3] = -1e30f;
            }
            mn0 = fmaxf(mn0, fmaxf(sA[nt][0], sA[nt][1]));
            mn1 = fmaxf(mn1, fmaxf(sA[nt][2], sA[nt][3]));
        }
        mn0 = fmaxf(mn0, __shfl_xor_sync(0xffffffffu, mn0, 1));
        mn0 = fmaxf(mn0, __shfl_xor_sync(0xffffffffu, mn0, 2));
        mn1 = fmaxf(mn1, __shfl_xor_sync(0xffffffffu, mn1, 1));
        mn1 = fmaxf(mn1, __shfl_xor_sync(0xffffffffu, mn1, 2));

        float c0 = __expf(m0 - mn0), c1 = __expf(m1 - mn1);
        m0 = mn0; m1 = mn1;

        // ---- P = exp(S - m) (rounded) -> psm; partial sums ----
        float ls0 = 0.f, ls1 = 0.f;
        #pragma unroll
        for (int nt = 0; nt < 8; nt++) {
            float p0 = to_tf32(__expf(sA[nt][0] - mn0));
            float p1 = to_tf32(__expf(sA[nt][1] - mn0));
            float p2 = to_tf32(__expf(sA[nt][2] - mn1));
            float p3 = to_tf32(__expf(sA[nt][3] - mn1));
            ls0 += p0 + p1; ls1 += p2 + p3;
            int cb = nt * 8 + 2 * cq;
            pb[r1 * 68 + cb]       = p0;
            pb[r1 * 68 + cb + 1]   = p1;
            pb[(r1 + 8) * 68 + cb]     = p2;
            pb[(r1 + 8) * 68 + cb + 1] = p3;
        }
        ls0 += __shfl_xor_sync(0xffffffffu, ls0, 1);
        ls0 += __shfl_xor_sync(0xffffffffu, ls0, 2);
        ls1 += __shfl_xor_sync(0xffffffffu, ls1, 1);
        ls1 += __shfl_xor_sync(0xffffffffu, ls1, 2);
        l0 = l0 * c0 + ls0;
        l1 = l1 * c1 + ls1;

        // ---- rescale O ----
        #pragma unroll
        for (int nt = 0; nt < 8; nt++) {
            oA[nt][0] *= c0; oA[nt][1] *= c0;
            oA[nt][2] *= c1; oA[nt][3] *= c1;
        }
        __syncwarp();

        // ---- O += P @ V ----
        #pragma unroll
        for (int ks = 0; ks < 8; ks++) {
            float af[4];
            af[0] = pb[r1 * 68 + ks * 8 + cq];
            af[1] = pb[(r1 + 8) * 68 + ks * 8 + cq];
            af[2] = pb[r1 * 68 + ks * 8 + cq + 4];
            af[3] = pb[(r1 + 8) * 68 + ks * 8 + cq + 4];
            const float* vb0 = vsm + (ks * 8 + cq) * 72 + r1;
            const float* vb1 = vsm + (ks * 8 + cq + 4) * 72 + r1;
            #pragma unroll
            for (int nt = 0; nt < 8; nt++) {
                float bf[2] = { vb0[nt * 8], vb1[nt * 8] };
                mma_f(oA[nt], af, bf);
            }
        }
    }

    // ---- epilogue ----
    float inv0 = 1.f / l0, inv1 = 1.f / l1;
    int gr0 = myqt * 64 + wg * 16 + r1;
    #pragma unroll
    for (int nt = 0; nt < 8; nt++) {
        int col = h * HD + nt * 8 + 2 * cq;
        float2 v0 = make_float2(to_tf32(oA[nt][0] * inv0), to_tf32(oA[nt][1] * inv0));
        float2 v1 = make_float2(to_tf32(oA[nt][2] * inv1), to_tf32(oA[nt][3] * inv1));
        *(float2*)&Oa[(size_t)gr0 * DMODEL + col] = v0;
        *(float2*)&Oa[(size_t)(gr0 + 8) * DMODEL + col] = v1;
    }
}

// ---------------------------------------------------------------------------
// RMSNorm: out exact, outT tf32-rounded
// ---------------------------------------------------------------------------
__global__ __launch_bounds__(256) void rmsnorm_k(const float* __restrict__ x,
                                                 const float* __restrict__ g,
                                                 float* __restrict__ out,
                                                 float* __restrict__ outT)
{
    int row = blockIdx.x;
    int tid = threadIdx.x;
    const float4* xr4 = (const float4*)(x + (size_t)row * DMODEL);
    const float4* g4  = (const float4*)g;

    float4 a = xr4[tid];
    float4 b = xr4[tid + 256];
    float s = a.x*a.x + a.y*a.y + a.z*a.z + a.w*a.w
            + b.x*b.x + b.y*b.y + b.z*b.z + b.w*b.w;
    #pragma unroll
    for (int off = 16; off > 0; off >>= 1) s += __shfl_xor_sync(0xffffffffu, s, off);

    __shared__ float red[8];
    __shared__ float inv_s;
    int wid = tid >> 5, lane = tid & 31;
    if (lane == 0) red[wid] = s;
    __syncthreads();
    if (tid == 0) {
        float t = 0.f;
        #pragma unroll
        for (int w = 0; w < 8; w++) t += red[w];
        inv_s = rsqrtf(t / (float)DMODEL + 1e-5f);
    }
    __syncthreads();
    float inv = inv_s;

    float4 ga = g4[tid], gb = g4[tid + 256];
    float4 ra, rb;
    ra.x = a.x*ga.x*inv; ra.y = a.y*ga.y*inv; ra.z = a.z*ga.z*inv; ra.w = a.w*ga.w*inv;
    rb.x = b.x*gb.x*inv; rb.y = b.y*gb.y*inv; rb.z = b.z*gb.z*inv; rb.w = b.w*gb.w*inv;
    ((float4*)(out + (size_t)row * DMODEL))[tid] = ra;
    ((float4*)(out + (size_t)row * DMODEL))[tid + 256] = rb;
    if (outT) {
        float4 ta = make_float4(to_tf32(ra.x), to_tf32(ra.y), to_tf32(ra.z), to_tf32(ra.w));
        float4 tb = make_float4(to_tf32(rb.x), to_tf32(rb.y), to_tf32(rb.z), to_tf32(rb.w));
        ((float4*)(outT + (size_t)row * DMODEL))[tid] = ta;
        ((float4*)(outT + (size_t)row * DMODEL))[tid + 256] = tb;
    }
}

// ---------------------------------------------------------------------------
// kernel_launch
// ---------------------------------------------------------------------------
extern "C" void kernel_launch(void* const* d_in, const int* in_sizes, int n_in,
                              void* d_out, int out_size)
{
    (void)in_sizes; (void)n_in; (void)out_size;
    const float* x  = (const float*)d_in[0];
    const float* g1 = (const float*)d_in[1];
    const float* wq = (const float*)d_in[2];
    const float* wk = (const float*)d_in[3];
    const float* wv = (const float*)d_in[4];
    const float* wo = (const float*)d_in[5];
    const float* g2 = (const float*)d_in[6];
    const float* wg = (const float*)d_in[7];
    const float* wu = (const float*)d_in[8];
    const float* wd = (const float*)d_in[9];
    float* out = (float*)d_out;

    float *xn, *xnt, *qkv, *att, *h2, *h3, *h3t, *gate, *gb, *rt;
    cudaGetSymbolAddress((void**)&xn,   g_xn);
    cudaGetSymbolAddress((void**)&xnt,  g_xnt);
    cudaGetSymbolAddress((void**)&qkv,  g_qkv);
    cudaGetSymbolAddress((void**)&att,  g_att);
    cudaGetSymbolAddress((void**)&h2,   g_h2);
    cudaGetSymbolAddress((void**)&h3,   g_h3);
    cudaGetSymbolAddress((void**)&h3t,  g_h3t);
    cudaGetSymbolAddress((void**)&gate, g_gate);
    cudaGetSymbolAddress((void**)&gb,   g_gb);
    cudaGetSymbolAddress((void**)&rt,   g_rt);

    cudaFuncSetAttribute(tgemm_k,   cudaFuncAttributeMaxDynamicSharedMemorySize, GSM_TOTAL);
    cudaFuncSetAttribute(attn_tc_k, cudaFuncAttributeMaxDynamicSharedMemorySize, ATT_SMEM_BYTES);

    // rope table + h1 = rmsnorm(x, g1)
    rope_table_k<<<T_LEN * 32 / 256, 256>>>(rt);
    rmsnorm_k<<<T_LEN, 256>>>(x, g1, xn, xnt);

    // qkv = h1t @ [wq|wk|wv], rope fused into epilogue
    tgemm_k<<<dim3(QKV_N/256, T_LEN/128), 256, GSM_TOTAL>>>(
        xnt, wq, wk, wv, qkv, T_LEN, QKV_N, DMODEL,
        DMODEL, 512, 512, 8, 10, nullptr, nullptr, 1, rt);

    // attention: 2 q-tiles per block share K/V
    attn_tc_k<<<dim3(T_LEN/128, NHEAD), 256, ATT_SMEM_BYTES>>>(qkv, att);

    // h2 = h1 + att @ wo
    tgemm_k<<<dim3(DMODEL/256, T_LEN/128), 256, GSM_TOTAL>>>(
        att, wo, wo, wo, h2, T_LEN, DMODEL, DMODEL,
        DMODEL, DMODEL, DMODEL, 9999, 9999, xn, nullptr, 0, nullptr);

    rmsnorm_k<<<T_LEN, 256>>>(h2, g2, h3, h3t);

    // gate = h3t @ wg
    tgemm_k<<<dim3(FF/256, T_LEN/128), 256, GSM_TOTAL>>>(
        h3t, wg, wg, wg, gate, T_LEN, FF, DMODEL,
        FF, FF, FF, 9999, 9999, nullptr, nullptr, 0, nullptr);

    // gb = tf32(silu(gate) * (h3t @ wu))   (silu fused into epilogue)
    tgemm_k<<<dim3(FF/256, T_LEN/128), 256, GSM_TOTAL>>>(
        h3t, wu, wu, wu, gb, T_LEN, FF, DMODEL,
        FF, FF, FF, 9999, 9999, nullptr, nullptr, 2, gate);

    // out = gb @ wd + h3 + x
    tgemm_k<<<dim3(DMODEL/256, T_LEN/128), 256, GSM_TOTAL>>>(
        gb, wd, wd, wd, out, T_LEN, DMODEL, FF,
        DMODEL, DMODEL, DMODEL, 9999, 9999, h3, x, 0, nullptr);
}

// round 13
// speedup vs baseline: 1.2058x; 1.0030x over previous
#include <cuda_runtime.h>
#include <cstdint>
#include <cstddef>

// ---------------------------------------------------------------------------
// LlamaDecoderLayer fp32. GEMMs + attention via portable mma.sync tf32.
// B operands stream directly from original W[K,N]. A fragments via ldmatrix.
// T=2048, D=2048, NH=32, NKV=8, HD=64, FF=8192.
// ---------------------------------------------------------------------------

#define T_LEN 2048
#define DMODEL 2048
#define NHEAD 32
#define NKV 8
#define HD 64
#define FF 8192
#define QKV_N 3072

// ---- scratch -------------------------------------------------------------
__device__ float g_xn  [T_LEN * DMODEL];     // h1 exact (residual)
__device__ float g_xnt [T_LEN * DMODEL];     // h1 tf32-rounded (GEMM A)
__device__ float g_qkv [T_LEN * QKV_N];
__device__ float g_att [T_LEN * DMODEL];     // attention out, tf32-rounded
__device__ float g_h2  [T_LEN * DMODEL];
__device__ float g_h3  [T_LEN * DMODEL];     // exact (residual)
__device__ float g_h3t [T_LEN * DMODEL];     // rounded (GEMM A)
__device__ float g_gate[T_LEN * FF];         // h3t @ wg (raw)
__device__ float g_gb  [T_LEN * FF];         // silu(gate)*up, rounded
__device__ float g_rt  [T_LEN * 64];         // rope table: (cos,sin) x 32 per row

// ---------------------------------------------------------------------------
// helpers
// ---------------------------------------------------------------------------
__device__ __forceinline__ uint32_t smem_u32(const void* p) {
    uint32_t a;
    asm("{ .reg .u64 t; cvta.to.shared.u64 t, %1; cvt.u32.u64 %0, t; }" : "=r"(a) : "l"(p));
    return a;
}
__device__ __forceinline__ float to_tf32(float x) {
    asm("cvt.rna.tf32.f32 %0, %1;" : "=f"(x) : "f"(x));
    return x;
}
#define CP16(sm_addr, gptr) \
    asm volatile("cp.async.cg.shared.global [%0], [%1], 16;" :: "r"(sm_addr), "l"(gptr))
#define CP_COMMIT() asm volatile("cp.async.commit_group;")
#define CP_WAIT1()  asm volatile("cp.async.wait_group 1;")

__device__ __forceinline__ void mma_f(float* c, const float* a, const float* b) {
    asm volatile("mma.sync.aligned.m16n8k8.row.col.f32.tf32.tf32.f32 "
                 "{%0,%1,%2,%3}, {%4,%5,%6,%7}, {%8,%9}, {%0,%1,%2,%3};"
                 : "+f"(c[0]), "+f"(c[1]), "+f"(c[2]), "+f"(c[3])
                 : "r"(__float_as_uint(a[0])), "r"(__float_as_uint(a[1])),
                   "r"(__float_as_uint(a[2])), "r"(__float_as_uint(a[3])),
                   "r"(__float_as_uint(b[0])), "r"(__float_as_uint(b[1])));
}
__device__ __forceinline__ void mma_u(float* c, const uint32_t* a, const float* b) {
    asm volatile("mma.sync.aligned.m16n8k8.row.col.f32.tf32.tf32.f32 "
                 "{%0,%1,%2,%3}, {%4,%5,%6,%7}, {%8,%9}, {%0,%1,%2,%3};"
                 : "+f"(c[0]), "+f"(c[1]), "+f"(c[2]), "+f"(c[3])
                 : "r"(a[0]), "r"(a[1]), "r"(a[2]), "r"(a[3]),
                   "r"(__float_as_uint(b[0])), "r"(__float_as_uint(b[1])));
}

// ---------------------------------------------------------------------------
// rope table: row t, d=0..31 -> (cos, sin)
// ---------------------------------------------------------------------------
__global__ __launch_bounds__(256) void rope_table_k(float* __restrict__ rt)
{
    int i = blockIdx.x * blockDim.x + threadIdx.x;   // over T*32
    int t = i >> 5, d = i & 31;
    double freq = exp((double)(-2.0 * d / 64.0) * 9.210340371976184);
    double si, co;
    sincos(freq * (double)t, &si, &co);
    ((float2*)rt)[i] = make_float2((float)co, (float)si);
}

// ---------------------------------------------------------------------------
// tf32 tensor-core GEMM (R10 config: BK=16, 3-stage) + ldmatrix A fragments.
// C[M,Nc] = A[M,K] @ Wsel[K,*]  (+add0 +add1). Epilogue: 0=none, 1=rope, 2=silu.
// ---------------------------------------------------------------------------
#define ASTRIDE 20
#define BSTRIDE 264
#define A_BYTES (128 * ASTRIDE * 4)          // 10240
#define B_BYTES (16 * BSTRIDE * 4)           // 16896
#define STG_B   (A_BYTES + B_BYTES)          // 27136
#define GSM_TOTAL (3 * STG_B)                // 81408

__global__ __launch_bounds__(256, 1) void tgemm_k(const float* __restrict__ A,
                                                  const float* __restrict__ B0,
                                                  const float* __restrict__ B1,
                                                  const float* __restrict__ B2,
                                                  float* __restrict__ C,
                                                  int M, int Nc, int K,
                                                  int sB0, int sB1, int sB2,
                                                  int blk1, int blk2,
                                                  const float* __restrict__ add0,
                                                  const float* __restrict__ add1,
                                                  int epi,
                                                  const float* __restrict__ epi_src)
{
    extern __shared__ char sm[];
    const uint32_t smb = smem_u32(sm);
    const int tid = threadIdx.x;
    const int wid = tid >> 5, lane = tid & 31;
    const int warp_m = wid & 1;
    const int warp_n = wid >> 1;
    const int bx = blockIdx.x;
    const int brow = blockIdx.y * 128;
    const int bcol = bx * 256;

    const float* B; int strideB, bcolB;
    if (bx < blk1)      { B = B0; strideB = sB0; bcolB = bx * 256; }
    else if (bx < blk2) { B = B1; strideB = sB1; bcolB = (bx - blk1) * 256; }
    else                { B = B2; strideB = sB2; bcolB = (bx - blk2) * 256; }

    // A loader: thread t -> row t>>1, cols (t&1)*8, 2x CP16
    const float* aG = A + (size_t)(brow + (tid >> 1)) * K + (tid & 1) * 8;
    const uint32_t sA0 = smb + (tid >> 1) * (ASTRIDE * 4) + (tid & 1) * 32;
    // B loader: thread t -> k-row t>>4, col chunk (t&15)*4, 4x CP16 at +64 floats
    const int bkr = tid >> 4, bc4 = (tid & 15) * 4;
    const float* bG = B + (size_t)bkr * strideB + bcolB + bc4;
    const uint32_t sB0a = smb + A_BYTES + (bkr * BSTRIDE + bc4) * 4;

    float c[4][8][4];
    #pragma unroll
    for (int mi = 0; mi < 4; mi++)
        #pragma unroll
        for (int ni = 0; ni < 8; ni++)
            #pragma unroll
            for (int j = 0; j < 4; j++) c[mi][ni][j] = 0.f;

    const int nk = K >> 4;

    #pragma unroll
    for (int p = 0; p < 2; p++) {
        const float* a0 = aG + p * 16;
        const float* b0 = bG + (size_t)p * 16 * strideB;
        uint32_t sa = sA0 + p * STG_B;
        uint32_t sb = sB0a + p * STG_B;
        CP16(sa, a0); CP16(sa + 16, a0 + 4);
        #pragma unroll
        for (int j = 0; j < 4; j++) CP16(sb + j * 256, b0 + j * 64);
        CP_COMMIT();
    }

    const int r1 = lane >> 2, cq = lane & 3;
    // ldmatrix lane offset: quadrant rows + float-col select
    const uint32_t lm_off =
        ((uint32_t)(warp_m * 64 + ((lane >> 3) & 1) * 8 + (lane & 7)) * ASTRIDE
         + (uint32_t)(lane >> 4) * 4) * 4;

    for (int kt = 0; kt < nk; kt++) {
        CP_WAIT1();
        __syncthreads();

        if (kt + 2 < nk) {
            int st = (kt + 2) % 3;
            const float* a0 = aG + (size_t)(kt + 2) * 16;
            const float* b0 = bG + (size_t)(kt + 2) * 16 * strideB;
            uint32_t sa = sA0 + st * STG_B;
            uint32_t sb = sB0a + st * STG_B;
            CP16(sa, a0); CP16(sa + 16, a0 + 4);
            #pragma unroll
            for (int j = 0; j < 4; j++) CP16(sb + j * 256, b0 + j * 64);
        }
        CP_COMMIT();

        const uint32_t stg = smb + (kt % 3) * STG_B;
        const float* Bs = (const float*)(sm + (kt % 3) * STG_B + A_BYTES);

        #pragma unroll
        for (int kk = 0; kk < 2; kk++) {
            uint32_t a[4][4];
            float b[8][2];
            const uint32_t abase = stg + lm_off + kk * 32;
            #pragma unroll
            for (int mi = 0; mi < 4; mi++) {
                asm volatile("ldmatrix.sync.aligned.m8n8.x4.shared.b16 {%0,%1,%2,%3}, [%4];"
                             : "=r"(a[mi][0]), "=r"(a[mi][1]),
                               "=r"(a[mi][2]), "=r"(a[mi][3])
                             : "r"(abase + (uint32_t)(mi * 16 * ASTRIDE * 4)));
            }
            const float* bp = Bs + (kk * 8 + cq) * BSTRIDE + warp_n * 64 + r1;
            #pragma unroll
            for (int ni = 0; ni < 8; ni++) {
                b[ni][0] = bp[ni * 8];
                b[ni][1] = bp[4 * BSTRIDE + ni * 8];
            }
            #pragma unroll
            for (int mi = 0; mi < 4; mi++)
                #pragma unroll
                for (int ni = 0; ni < 8; ni++)
                    mma_u(c[mi][ni], a[mi], b[ni]);
        }
    }

    // ---- epilogue ----
    #pragma unroll
    for (int mi = 0; mi < 4; mi++) {
        #pragma unroll
        for (int part = 0; part < 2; part++) {
            int r = brow + warp_m * 64 + mi * 16 + r1 + part * 8;
            size_t rowbase = (size_t)r * Nc;
            #pragma unroll
            for (int ni = 0; ni < 8; ni++) {
                int col = bcol + warp_n * 64 + ni * 8 + cq * 2;
                float2 v = make_float2(c[mi][ni][part * 2], c[mi][ni][part * 2 + 1]);
                if (epi == 1) {
                    if (col < 2560) {   // rope on q (0..2047) and k (2048..2559)
                        int dp = (col & 63) >> 1;
                        float2 cssn = ((const float2*)epi_src)[r * 32 + dp];
                        float x1 = v.x, x2 = v.y;
                        v.x = x1 * cssn.x - x2 * cssn.y;
                        v.y = x2 * cssn.x + x1 * cssn.y;
                    }
                } else if (epi == 2) {  // v = up; combine with gate
                    const float2 gt = *(const float2*)&epi_src[rowbase + col];
                    v.x = to_tf32(gt.x / (1.f + __expf(-gt.x)) * v.x);
                    v.y = to_tf32(gt.y / (1.f + __expf(-gt.y)) * v.y);
                }
                if (add0) { const float2 a2 = *(const float2*)&add0[rowbase + col];
                            v.x += a2.x; v.y += a2.y; }
                if (add1) { const float2 a2 = *(const float2*)&add1[rowbase + col];
                            v.x += a2.x; v.y += a2.y; }
                *(float2*)&C[rowbase + col] = v;
            }
        }
    }
}

// ---------------------------------------------------------------------------
// Tensor-core flash attention (causal GQA) — R10 version (known 205us).
// Block = 64 q rows x 1 head, 4 warps. smem: qsm 64x68 | ksm 64x68 |
// vsm 64x72 | psm 4x16x68
// ---------------------------------------------------------------------------
#define ATT_SMEM_FLOATS (4352 + 4352 + 4608 + 4352)
#define ATT_SMEM_BYTES  (ATT_SMEM_FLOATS * 4)

__global__ __launch_bounds__(128) void attn_tc_k(const float* __restrict__ QKV,
                                                 float* __restrict__ Oa)
{
    extern __shared__ float s[];
    float* qsm = s;                  // [64][68]
    float* ksm = s + 4352;           // [64][68]
    float* vsm = s + 8704;           // [64][72]
    float* psm = s + 13312;          // [4][16][68]

    const int tid = threadIdx.x;
    const int w = tid >> 5, lane = tid & 31;
    const int r1 = lane >> 2, cq = lane & 3;
    const int qt = blockIdx.x, h = blockIdx.y;
    const int kvh = h >> 2;

    {
        const float* qb = QKV + (size_t)(qt * 64) * QKV_N + h * HD;
        for (int t = tid; t < 1024; t += 128) {
            int i = t >> 4, d4 = (t & 15) * 4;
            float4 v4 = *(const float4*)(qb + (size_t)i * QKV_N + d4);
            v4.x = to_tf32(v4.x); v4.y = to_tf32(v4.y);
            v4.z = to_tf32(v4.z); v4.w = to_tf32(v4.w);
            *(float4*)(qsm + i * 68 + d4) = v4;
        }
    }
    __syncthreads();

    float qf[8][4];
    {
        const float* qb = qsm + (w * 16 + r1) * 68 + cq;
        #pragma unroll
        for (int ks = 0; ks < 8; ks++) {
            qf[ks][0] = qb[ks * 8];
            qf[ks][1] = qb[8 * 68 + ks * 8];
            qf[ks][2] = qb[ks * 8 + 4];
            qf[ks][3] = qb[8 * 68 + ks * 8 + 4];
        }
    }

    float oA[8][4];
    #pragma unroll
    for (int nt = 0; nt < 8; nt++)
        #pragma unroll
        for (int j = 0; j < 4; j++) oA[nt][j] = 0.f;
    float m0 = -1e30f, m1 = -1e30f, l0 = 0.f, l1 = 0.f;

    float* pb = psm + w * 16 * 68;

    for (int jt = 0; jt <= qt; jt++) {
        __syncthreads();
        {
            const float* kb = QKV + (size_t)(jt * 64) * QKV_N + DMODEL + kvh * HD;
            const float* vb = kb + 512;
            for (int t = tid; t < 1024; t += 128) {
                int i = t >> 4, d4 = (t & 15) * 4;
                float4 k4 = *(const float4*)(kb + (size_t)i * QKV_N + d4);
                k4.x = to_tf32(k4.x); k4.y = to_tf32(k4.y);
                k4.z = to_tf32(k4.z); k4.w = to_tf32(k4.w);
                *(float4*)(ksm + i * 68 + d4) = k4;
                float4 v4 = *(const float4*)(vb + (size_t)i * QKV_N + d4);
                v4.x = to_tf32(v4.x); v4.y = to_tf32(v4.y);
                v4.z = to_tf32(v4.z); v4.w = to_tf32(v4.w);
                *(float4*)(vsm + i * 72 + d4) = v4;
            }
        }
        __syncthreads();

        float sA[8][4];
        #pragma unroll
        for (int nt = 0; nt < 8; nt++) {
            float acc[4] = {0.f, 0.f, 0.f, 0.f};
            const float* kbp = ksm + (nt * 8 + r1) * 68 + cq;
            #pragma unroll
            for (int ks = 0; ks < 8; ks++) {
                float bf[2] = { kbp[ks * 8], kbp[ks * 8 + 4] };
                mma_f(acc, qf[ks], bf);
            }
            sA[nt][0] = acc[0]; sA[nt][1] = acc[1];
            sA[nt][2] = acc[2]; sA[nt][3] = acc[3];
        }

        float mn0 = m0, mn1 = m1;
        const int row0 = w * 16 + r1, row1 = row0 + 8;
        #pragma unroll
        for (int nt = 0; nt < 8; nt++) {
            #pragma unroll
            for (int j = 0; j < 4; j++) sA[nt][j] *= 0.125f;
            if (jt == qt) {
                int colb = nt * 8 + 2 * cq;
                if (colb     > row0) sA[nt][0] = -1e30f;
                if (colb + 1 > row0) sA[nt][1] = -1e30f;
                if (colb     > row1) sA[nt][2] = -1e30f;
                if (colb + 1 > row1) sA[nt][3] = -1e30f;
            }
            mn0 = fmaxf(mn0, fmaxf(sA[nt][0], sA[nt][1]));
            mn1 = fmaxf(mn1, fmaxf(sA[nt][2], sA[nt][3]));
        }
        mn0 = fmaxf(mn0, __shfl_xor_sync(0xffffffffu, mn0, 1));
        mn0 = fmaxf(mn0, __shfl_xor_sync(0xffffffffu, mn0, 2));
        mn1 = fmaxf(mn1, __shfl_xor_sync(0xffffffffu, mn1, 1));
        mn1 = fmaxf(mn1, __shfl_xor_sync(0xffffffffu, mn1, 2));

        float c0 = __expf(m0 - mn0), c1 = __expf(m1 - mn1);
        m0 = mn0; m1 = mn1;

        float ls0 = 0.f, ls1 = 0.f;
        #pragma unroll
        for (int nt = 0; nt < 8; nt++) {
            float p0 = to_tf32(__expf(sA[nt][0] - mn0));
            float p1 = to_tf32(__expf(sA[nt][1] - mn0));
            float p2 = to_tf32(__expf(sA[nt][2] - mn1));
            float p3 = to_tf32(__expf(sA[nt][3] - mn1));
            ls0 += p0 + p1; ls1 += p2 + p3;
            int cb = nt * 8 + 2 * cq;
            pb[r1 * 68 + cb]       = p0;
            pb[r1 * 68 + cb + 1]   = p1;
            pb[(r1 + 8) * 68 + cb]     = p2;
            pb[(r1 + 8) * 68 + cb + 1] = p3;
        }
        ls0 += __shfl_xor_sync(0xffffffffu, ls0, 1);
        ls0 += __shfl_xor_sync(0xffffffffu, ls0, 2);
        ls1 += __shfl_xor_sync(0xffffffffu, ls1, 1);
        ls1 += __shfl_xor_sync(0xffffffffu, ls1, 2);
        l0 = l0 * c0 + ls0;
        l1 = l1 * c1 + ls1;

        #pragma unroll
        for (int nt = 0; nt < 8; nt++) {
            oA[nt][0] *= c0; oA[nt][1] *= c0;
            oA[nt][2] *= c1; oA[nt][3] *= c1;
        }
        __syncwarp();

        #pragma unroll
        for (int ks = 0; ks < 8; ks++) {
            float af[4];
            af[0] = pb[r1 * 68 + ks * 8 + cq];
            af[1] = pb[(r1 + 8) * 68 + ks * 8 + cq];
            af[2] = pb[r1 * 68 + ks * 8 + cq + 4];
            af[3] = pb[(r1 + 8) * 68 + ks * 8 + cq + 4];
            const float* vb0 = vsm + (ks * 8 + cq) * 72 + r1;
            const float* vb1 = vsm + (ks * 8 + cq + 4) * 72 + r1;
            #pragma unroll
            for (int nt = 0; nt < 8; nt++) {
                float bf[2] = { vb0[nt * 8], vb1[nt * 8] };
                mma_f(oA[nt], af, bf);
            }
        }
    }

    float inv0 = 1.f / l0, inv1 = 1.f / l1;
    int gr0 = qt * 64 + w * 16 + r1;
    #pragma unroll
    for (int nt = 0; nt < 8; nt++) {
        int col = h * HD + nt * 8 + 2 * cq;
        float2 v0 = make_float2(to_tf32(oA[nt][0] * inv0), to_tf32(oA[nt][1] * inv0));
        float2 v1 = make_float2(to_tf32(oA[nt][2] * inv1), to_tf32(oA[nt][3] * inv1));
        *(float2*)&Oa[(size_t)gr0 * DMODEL + col] = v0;
        *(float2*)&Oa[(size_t)(gr0 + 8) * DMODEL + col] = v1;
    }
}

// ---------------------------------------------------------------------------
// RMSNorm: out exact, outT tf32-rounded
// ---------------------------------------------------------------------------
__global__ __launch_bounds__(256) void rmsnorm_k(const float* __restrict__ x,
                                                 const float* __restrict__ g,
                                                 float* __restrict__ out,
                                                 float* __restrict__ outT)
{
    int row = blockIdx.x;
    int tid = threadIdx.x;
    const float4* xr4 = (const float4*)(x + (size_t)row * DMODEL);
    const float4* g4  = (const float4*)g;

    float4 a = xr4[tid];
    float4 b = xr4[tid + 256];
    float s = a.x*a.x + a.y*a.y + a.z*a.z + a.w*a.w
            + b.x*b.x + b.y*b.y + b.z*b.z + b.w*b.w;
    #pragma unroll
    for (int off = 16; off > 0; off >>= 1) s += __shfl_xor_sync(0xffffffffu, s, off);

    __shared__ float red[8];
    __shared__ float inv_s;
    int wid = tid >> 5, lane = tid & 31;
    if (lane == 0) red[wid] = s;
    __syncthreads();
    if (tid == 0) {
        float t = 0.f;
        #pragma unroll
        for (int w = 0; w < 8; w++) t += red[w];
        inv_s = rsqrtf(t / (float)DMODEL + 1e-5f);
    }
    __syncthreads();
    float inv = inv_s;

    float4 ga = g4[tid], gb = g4[tid + 256];
    float4 ra, rb;
    ra.x = a.x*ga.x*inv; ra.y = a.y*ga.y*inv; ra.z = a.z*ga.z*inv; ra.w = a.w*ga.w*inv;
    rb.x = b.x*gb.x*inv; rb.y = b.y*gb.y*inv; rb.z = b.z*gb.z*inv; rb.w = b.w*gb.w*inv;
    ((float4*)(out + (size_t)row * DMODEL))[tid] = ra;
    ((float4*)(out + (size_t)row * DMODEL))[tid + 256] = rb;
    if (outT) {
        float4 ta = make_float4(to_tf32(ra.x), to_tf32(ra.y), to_tf32(ra.z), to_tf32(ra.w));
        float4 tb = make_float4(to_tf32(rb.x), to_tf32(rb.y), to_tf32(rb.z), to_tf32(rb.w));
        ((float4*)(outT + (size_t)row * DMODEL))[tid] = ta;
        ((float4*)(outT + (size_t)row * DMODEL))[tid + 256] = tb;
    }
}

// ---------------------------------------------------------------------------
// kernel_launch
// ---------------------------------------------------------------------------
extern "C" void kernel_launch(void* const* d_in, const int* in_sizes, int n_in,
                              void* d_out, int out_size)
{
    (void)in_sizes; (void)n_in; (void)out_size;
    const float* x  = (const float*)d_in[0];
    const float* g1 = (const float*)d_in[1];
    const float* wq = (const float*)d_in[2];
    const float* wk = (const float*)d_in[3];
    const float* wv = (const float*)d_in[4];
    const float* wo = (const float*)d_in[5];
    const float* g2 = (const float*)d_in[6];
    const float* wg = (const float*)d_in[7];
    const float* wu = (const float*)d_in[8];
    const float* wd = (const float*)d_in[9];
    float* out = (float*)d_out;

    float *xn, *xnt, *qkv, *att, *h2, *h3, *h3t, *gate, *gb, *rt;
    cudaGetSymbolAddress((void**)&xn,   g_xn);
    cudaGetSymbolAddress((void**)&xnt,  g_xnt);
    cudaGetSymbolAddress((void**)&qkv,  g_qkv);
    cudaGetSymbolAddress((void**)&att,  g_att);
    cudaGetSymbolAddress((void**)&h2,   g_h2);
    cudaGetSymbolAddress((void**)&h3,   g_h3);
    cudaGetSymbolAddress((void**)&h3t,  g_h3t);
    cudaGetSymbolAddress((void**)&gate, g_gate);
    cudaGetSymbolAddress((void**)&gb,   g_gb);
    cudaGetSymbolAddress((void**)&rt,   g_rt);

    cudaFuncSetAttribute(tgemm_k,   cudaFuncAttributeMaxDynamicSharedMemorySize, GSM_TOTAL);
    cudaFuncSetAttribute(attn_tc_k, cudaFuncAttributeMaxDynamicSharedMemorySize, ATT_SMEM_BYTES);

    // rope table + h1 = rmsnorm(x, g1)
    rope_table_k<<<T_LEN * 32 / 256, 256>>>(rt);
    rmsnorm_k<<<T_LEN, 256>>>(x, g1, xn, xnt);

    // qkv = h1t @ [wq|wk|wv], rope fused into epilogue
    tgemm_k<<<dim3(QKV_N/256, T_LEN/128), 256, GSM_TOTAL>>>(
        xnt, wq, wk, wv, qkv, T_LEN, QKV_N, DMODEL,
        DMODEL, 512, 512, 8, 10, nullptr, nullptr, 1, rt);

    attn_tc_k<<<dim3(T_LEN/64, NHEAD), 128, ATT_SMEM_BYTES>>>(qkv, att);

    // h2 = h1 + att @ wo
    tgemm_k<<<dim3(DMODEL/256, T_LEN/128), 256, GSM_TOTAL>>>(
        att, wo, wo, wo, h2, T_LEN, DMODEL, DMODEL,
        DMODEL, DMODEL, DMODEL, 9999, 9999, xn, nullptr, 0, nullptr);

    rmsnorm_k<<<T_LEN, 256>>>(h2, g2, h3, h3t);

    // gate = h3t @ wg
    tgemm_k<<<dim3(FF/256, T_LEN/128), 256, GSM_TOTAL>>>(
        h3t, wg, wg, wg, gate, T_LEN, FF, DMODEL,
        FF, FF, FF, 9999, 9999, nullptr, nullptr, 0, nullptr);

    // gb = tf32(silu(gate) * (h3t @ wu))   (silu fused into epilogue)
    tgemm_k<<<dim3(FF/256, T_LEN/128), 256, GSM_TOTAL>>>(
        h3t, wu, wu, wu, gb, T_LEN, FF, DMODEL,
        FF, FF, FF, 9999, 9999, nullptr, nullptr, 2, gate);

    // out = gb @ wd + h3 + x
    tgemm_k<<<dim3(DMODEL/256, T_LEN/128), 256, GSM_TOTAL>>>(
        gb, wd, wd, wd, out, T_LEN, DMODEL, FF,
        DMODEL, DMODEL, DMODEL, 9999, 9999, h3, x, 0, nullptr);
}